// round 6
// baseline (speedup 1.0000x reference)
#include <cuda_runtime.h>
#include <stdint.h>

#define NN 100000
#define NE 1600000
#define NF 256
#define NH 64
#define NHTOT (NN * NH)          // 6,400,000

// Scratch (static device globals — zero-initialized at load; each call restores
// the zero state itself so graph replays are deterministic).
__device__ __align__(16) float g_support[NHTOT];   // x @ W
__device__ __align__(16) float g_agg[NHTOT];       // segment_sum (bias cancels in BN)
__device__ __align__(16) unsigned char g_mask[NHTOT]; // dropout keep mask
__device__ double g_sum[NH];
__device__ double g_sumsq[NH];
__device__ float g_scale[NH];
__device__ float g_shift[NH];
__device__ unsigned int g_arrive;                  // colstats completion counter

// ---------------------------------------------------------------------------
// GEMM: support[NN,64] = x[NN,256] @ W[256,64]
// Block tile 128x64, 128 threads, 8x8 micro-tile, K-step 16 (scalar FFMA; the
// f32x2 packed variant measured 2.5x SLOWER in R3).
// ---------------------------------------------------------------------------
__global__ __launch_bounds__(128) void k_gemm(const float* __restrict__ x,
                                              const float* __restrict__ W) {
    __shared__ float As[16][132];   // [k][row]
    __shared__ float Bs[16][64];    // [k][col]

    const int tid = threadIdx.x;
    const int tx = tid & 7;     // output cols tx*8 .. tx*8+7
    const int ty = tid >> 3;    // output rows ty*8 .. ty*8+7
    const int rowBase = blockIdx.x * 128;

    float acc[8][8];
#pragma unroll
    for (int i = 0; i < 8; i++)
#pragma unroll
        for (int j = 0; j < 8; j++) acc[i][j] = 0.0f;

    for (int k0 = 0; k0 < NF; k0 += 16) {
#pragma unroll
        for (int i = 0; i < 4; i++) {
            int idx = i * 512 + tid * 4;
            int r = idx >> 4;
            int kk = idx & 15;
            float4 v = make_float4(0.f, 0.f, 0.f, 0.f);
            int gr = rowBase + r;
            if (gr < NN)
                v = *reinterpret_cast<const float4*>(x + gr * NF + k0 + kk);
            As[kk + 0][r] = v.x;
            As[kk + 1][r] = v.y;
            As[kk + 2][r] = v.z;
            As[kk + 3][r] = v.w;
        }
#pragma unroll
        for (int i = 0; i < 2; i++) {
            int idx = i * 512 + tid * 4;
            int kk = idx >> 6;
            int c = idx & 63;
            *reinterpret_cast<float4*>(&Bs[kk][c]) =
                *reinterpret_cast<const float4*>(W + (k0 + kk) * NH + c);
        }
        __syncthreads();

#pragma unroll
        for (int kk = 0; kk < 16; kk++) {
            float a[8], bb[8];
            *reinterpret_cast<float4*>(&a[0]) = *reinterpret_cast<const float4*>(&As[kk][ty * 8]);
            *reinterpret_cast<float4*>(&a[4]) = *reinterpret_cast<const float4*>(&As[kk][ty * 8 + 4]);
            *reinterpret_cast<float4*>(&bb[0]) = *reinterpret_cast<const float4*>(&Bs[kk][tx * 8]);
            *reinterpret_cast<float4*>(&bb[4]) = *reinterpret_cast<const float4*>(&Bs[kk][tx * 8 + 4]);
#pragma unroll
            for (int i = 0; i < 8; i++)
#pragma unroll
                for (int j = 0; j < 8; j++) acc[i][j] = fmaf(a[i], bb[j], acc[i][j]);
        }
        __syncthreads();
    }

#pragma unroll
    for (int i = 0; i < 8; i++) {
        int gr = rowBase + ty * 8 + i;
        if (gr < NN) {
            *reinterpret_cast<float4*>(g_support + gr * NH + tx * 8) =
                make_float4(acc[i][0], acc[i][1], acc[i][2], acc[i][3]);
            *reinterpret_cast<float4*>(g_support + gr * NH + tx * 8 + 4) =
                make_float4(acc[i][4], acc[i][5], acc[i][6], acc[i][7]);
        }
    }
}

// ---------------------------------------------------------------------------
// JAX threefry dropout bits (partitionable layout): counter64 = i -> (0, i),
// key(42) -> (0, 42), 20 rounds, 32-bit lane fold x0^x1.
// ---------------------------------------------------------------------------
#define TF_R(r) { x0 += x1; x1 = __funnelshift_l(x1, x1, (r)); x1 ^= x0; }

__device__ __forceinline__ uint32_t tf_bits(uint32_t i) {
    const uint32_t ks0 = 0u, ks1 = 42u, ks2 = 0x1BD11BDAu ^ 42u;
    uint32_t x0 = ks0;
    uint32_t x1 = i + ks1;
    TF_R(13) TF_R(15) TF_R(26) TF_R(6)
    x0 += ks1; x1 += ks2 + 1u;
    TF_R(17) TF_R(29) TF_R(16) TF_R(24)
    x0 += ks2; x1 += ks0 + 2u;
    TF_R(13) TF_R(15) TF_R(26) TF_R(6)
    x0 += ks0; x1 += ks1 + 3u;
    TF_R(17) TF_R(29) TF_R(16) TF_R(24)
    x0 += ks1; x1 += ks2 + 4u;
    TF_R(13) TF_R(15) TF_R(26) TF_R(6)
    x0 += ks2; x1 += ks0 + 5u;
    return x0 ^ x1;
}

__device__ __forceinline__ unsigned char tf_keep(uint32_t i) {
    uint32_t bits = tf_bits(i);
    float u = __uint_as_float((bits >> 9) | 0x3f800000u) - 1.0f;
    return (u < 0.7f) ? 1 : 0;
}

// ---------------------------------------------------------------------------
// Fused scatter + dropout-mask generation.
// First MASKB blocks: pure-ALU threefry mask gen (overlaps scatter's LSU work).
// Remaining blocks: agg[row[e]] += ew[e] * support[col[e]] (16 thr/edge, v4 red)
// ---------------------------------------------------------------------------
#define MASKB (NHTOT / 4 / 256)                   // 6250
#define SCATB (NE * 16 / 256)                     // 100000

__global__ void k_scatter(const int* __restrict__ row, const int* __restrict__ col,
                          const float* __restrict__ ew) {
    if (blockIdx.x < MASKB) {
        int base = (blockIdx.x * 256 + threadIdx.x) * 4;
        uchar4 m;
        m.x = tf_keep((uint32_t)base);
        m.y = tf_keep((uint32_t)base + 1u);
        m.z = tf_keep((uint32_t)base + 2u);
        m.w = tf_keep((uint32_t)base + 3u);
        *reinterpret_cast<uchar4*>(g_mask + base) = m;
        return;
    }
    int t = (blockIdx.x - MASKB) * 256 + threadIdx.x;
    int e = t >> 4;
    int l = t & 15;
    int c = __ldg(col + e);
    int r = __ldg(row + e);
    float w = __ldg(ew + e);
    float4 v = __ldg(reinterpret_cast<const float4*>(g_support) + c * 16 + l);
    float* dst = g_agg + r * 64 + l * 4;
    asm volatile("red.global.add.v4.f32 [%0], {%1, %2, %3, %4};"
                 :: "l"(dst), "f"(v.x * w), "f"(v.y * w), "f"(v.z * w), "f"(v.w * w)
                 : "memory");
}

// ---------------------------------------------------------------------------
// BN column stats (float4, high MLP) + fused finalize in the last block.
// ---------------------------------------------------------------------------
#define NSTAT_BLK 1184

__global__ __launch_bounds__(256) void k_colstats(const float* __restrict__ gamma,
                                                  const float* __restrict__ beta) {
    int j4 = threadIdx.x & 15;    // which float4 within the 64-col row
    int grp = threadIdx.x >> 4;   // 0..15: row group
    float4 s = make_float4(0.f, 0.f, 0.f, 0.f);
    float4 q = make_float4(0.f, 0.f, 0.f, 0.f);
    for (int r = blockIdx.x * 16 + grp; r < NN; r += NSTAT_BLK * 16) {
        float4 v = *reinterpret_cast<const float4*>(g_agg + r * 64 + j4 * 4);
        s.x += v.x; s.y += v.y; s.z += v.z; s.w += v.w;
        q.x = fmaf(v.x, v.x, q.x); q.y = fmaf(v.y, v.y, q.y);
        q.z = fmaf(v.z, v.z, q.z); q.w = fmaf(v.w, v.w, q.w);
    }
    __shared__ float ss[16][68], sq[16][68];
    __shared__ bool s_last;
    *reinterpret_cast<float4*>(&ss[grp][j4 * 4]) = s;
    *reinterpret_cast<float4*>(&sq[grp][j4 * 4]) = q;
    __syncthreads();
    if (threadIdx.x < 64) {
        int j = threadIdx.x;
        float S = 0.f, Q = 0.f;
#pragma unroll
        for (int g = 0; g < 16; g++) { S += ss[g][j]; Q += sq[g][j]; }
        atomicAdd(&g_sum[j], (double)S);
        atomicAdd(&g_sumsq[j], (double)Q);
    }
    __syncthreads();
    if (threadIdx.x == 0) {
        __threadfence();
        unsigned int prev = atomicAdd(&g_arrive, 1u);
        s_last = (prev == NSTAT_BLK - 1);
    }
    __syncthreads();
    if (s_last) {
        if (threadIdx.x < NH) {
            int j = threadIdx.x;
            double mean = g_sum[j] / (double)NN;
            double var = g_sumsq[j] / (double)NN - mean * mean;
            float sc = (float)((double)gamma[j] * rsqrt(var + 1e-5));
            g_scale[j] = sc;
            g_shift[j] = beta[j] - (float)mean * sc;
            g_sum[j] = 0.0;
            g_sumsq[j] = 0.0;
        }
        if (threadIdx.x == 64) g_arrive = 0u;
    }
}

// ---------------------------------------------------------------------------
// Epilogue: BN affine + ReLU + precomputed dropout mask; re-zeroes g_agg.
// ---------------------------------------------------------------------------
__global__ void k_out(float* __restrict__ out) {
    int base = (blockIdx.x * blockDim.x + threadIdx.x) * 4;
    if (base >= NHTOT) return;
    float4 v4 = *reinterpret_cast<const float4*>(g_agg + base);
    *reinterpret_cast<float4*>(g_agg + base) = make_float4(0.f, 0.f, 0.f, 0.f);
    uchar4 m = *reinterpret_cast<const uchar4*>(g_mask + base);
    int j = base & 63;
    const float inv_keep = 1.0f / 0.7f;
    float4 r;
    r.x = m.x ? fmaxf(fmaf(v4.x, g_scale[j + 0], g_shift[j + 0]), 0.f) * inv_keep : 0.f;
    r.y = m.y ? fmaxf(fmaf(v4.y, g_scale[j + 1], g_shift[j + 1]), 0.f) * inv_keep : 0.f;
    r.z = m.z ? fmaxf(fmaf(v4.z, g_scale[j + 2], g_shift[j + 2]), 0.f) * inv_keep : 0.f;
    r.w = m.w ? fmaxf(fmaf(v4.w, g_scale[j + 3], g_shift[j + 3]), 0.f) * inv_keep : 0.f;
    *reinterpret_cast<float4*>(out + base) = r;
}

// ---------------------------------------------------------------------------
extern "C" void kernel_launch(void* const* d_in, const int* in_sizes, int n_in,
                              void* d_out, int out_size) {
    const float* x     = (const float*)d_in[0];
    const int*   row   = (const int*)d_in[1];
    const int*   col   = (const int*)d_in[2];
    const float* ew    = (const float*)d_in[3];
    const float* W     = (const float*)d_in[4];
    const float* gamma = (const float*)d_in[6];
    const float* beta  = (const float*)d_in[7];
    float* out = (float*)d_out;

    k_gemm<<<(NN + 127) / 128, 128>>>(x, W);
    k_scatter<<<MASKB + SCATB, 256>>>(row, col, ew);
    k_colstats<<<NSTAT_BLK, 256>>>(gamma, beta);
    k_out<<<(NHTOT / 4 + 255) / 256, 256>>>(out);
}

// round 10
// speedup vs baseline: 1.1757x; 1.1757x over previous
#include <cuda_runtime.h>
#include <stdint.h>

#define NN 100000
#define NE 1600000
#define NF 256
#define NH 64
#define NHTOT (NN * NH)          // 6,400,000

// Scratch (static device globals — zero-initialized at load; each call restores
// the zero state itself so graph replays are deterministic).
__device__ __align__(16) float g_support[NHTOT];   // x @ W
__device__ __align__(16) float g_agg[NHTOT];       // segment_sum (bias cancels in BN)
__device__ double g_sum[NH];
__device__ double g_sumsq[NH];
__device__ float g_scale[NH];
__device__ float g_shift[NH];
__device__ unsigned int g_arrive;                  // colstats completion counter

// ---------------------------------------------------------------------------
// GEMM: support[NN,64] = x[NN,256] @ W[256,64] via mma.sync tf32 (m16n8k8).
// CTA: 256 threads / 8 warps; tile 128x64; warp w -> rows 16w..16w+15.
// K in 8 chunks of 32. Inputs rounded to tf32 (cvt.rna) at SMEM staging.
// ---------------------------------------------------------------------------
__device__ __forceinline__ float tf32r(float f) {
    uint32_t o;
    asm("cvt.rna.tf32.f32 %0, %1;" : "=r"(o) : "f"(f));
    return __uint_as_float(o);
}

__global__ __launch_bounds__(256) void k_gemm(const float* __restrict__ x,
                                              const float* __restrict__ W) {
    __shared__ float As[128][36];   // stride 36: banks 4r+c -> conflict-free frags
    __shared__ float Bs[32][68];    // stride 68: <=2-way

    const int tid = threadIdx.x;
    const int lane = tid & 31;
    const int warp = tid >> 5;
    const int rowBase = blockIdx.x * 128;
    const int r4 = lane >> 2;       // 0..7
    const int c4 = lane & 3;        // 0..3

    float d[8][4];
#pragma unroll
    for (int n = 0; n < 8; n++)
#pragma unroll
        for (int i = 0; i < 4; i++) d[n][i] = 0.0f;

    for (int ch = 0; ch < 8; ch++) {
        const int k0 = ch * 32;
        // A chunk: 128 rows x 32 floats (1024 float4, 4/thread)
#pragma unroll
        for (int i = 0; i < 4; i++) {
            int idx = i * 256 + tid;
            int r = idx >> 3, q = idx & 7;
            float4 v = make_float4(0.f, 0.f, 0.f, 0.f);
            if (rowBase + r < NN)
                v = __ldg(reinterpret_cast<const float4*>(x + (rowBase + r) * NF + k0) + q);
            v.x = tf32r(v.x); v.y = tf32r(v.y); v.z = tf32r(v.z); v.w = tf32r(v.w);
            *reinterpret_cast<float4*>(&As[r][q * 4]) = v;
        }
        // B chunk: 32 k x 64 n (512 float4, 2/thread)
#pragma unroll
        for (int i = 0; i < 2; i++) {
            int idx = i * 256 + tid;
            int r = idx >> 4, q = idx & 15;
            float4 v = __ldg(reinterpret_cast<const float4*>(W + (k0 + r) * NH) + q);
            v.x = tf32r(v.x); v.y = tf32r(v.y); v.z = tf32r(v.z); v.w = tf32r(v.w);
            *reinterpret_cast<float4*>(&Bs[r][q * 4]) = v;
        }
        __syncthreads();

        const int wr = warp * 16;
#pragma unroll
        for (int k8 = 0; k8 < 4; k8++) {
            const int kc = k8 * 8;
            uint32_t a0 = __float_as_uint(As[wr + r4][kc + c4]);
            uint32_t a1 = __float_as_uint(As[wr + r4 + 8][kc + c4]);
            uint32_t a2 = __float_as_uint(As[wr + r4][kc + c4 + 4]);
            uint32_t a3 = __float_as_uint(As[wr + r4 + 8][kc + c4 + 4]);
#pragma unroll
            for (int n = 0; n < 8; n++) {
                uint32_t b0 = __float_as_uint(Bs[kc + c4][n * 8 + r4]);
                uint32_t b1 = __float_as_uint(Bs[kc + c4 + 4][n * 8 + r4]);
                asm volatile(
                    "mma.sync.aligned.m16n8k8.row.col.f32.tf32.tf32.f32 "
                    "{%0,%1,%2,%3}, {%4,%5,%6,%7}, {%8,%9}, {%0,%1,%2,%3};"
                    : "+f"(d[n][0]), "+f"(d[n][1]), "+f"(d[n][2]), "+f"(d[n][3])
                    : "r"(a0), "r"(a1), "r"(a2), "r"(a3), "r"(b0), "r"(b1));
            }
        }
        __syncthreads();
    }

    // Store: thread holds rows (wr+r4, wr+r4+8), cols n*8 + 2*c4 (+1)
    const int wr = warp * 16;
#pragma unroll
    for (int n = 0; n < 8; n++) {
        int gr = rowBase + wr + r4;
        int col = n * 8 + 2 * c4;
        if (gr < NN)
            *reinterpret_cast<float2*>(g_support + gr * NH + col) =
                make_float2(d[n][0], d[n][1]);
        if (gr + 8 < NN)
            *reinterpret_cast<float2*>(g_support + (gr + 8) * NH + col) =
                make_float2(d[n][2], d[n][3]);
    }
}

// ---------------------------------------------------------------------------
// Scatter: agg[row[e]] += ew[e] * support[col[e]]   (16 threads/edge, v4 red)
// ---------------------------------------------------------------------------
__global__ void k_scatter(const int* __restrict__ row, const int* __restrict__ col,
                          const float* __restrict__ ew) {
    int t = blockIdx.x * blockDim.x + threadIdx.x;
    int e = t >> 4;
    if (e >= NE) return;
    int l = t & 15;
    int c = __ldg(col + e);
    int r = __ldg(row + e);
    float w = __ldg(ew + e);
    float4 v = __ldg(reinterpret_cast<const float4*>(g_support) + c * 16 + l);
    float* dst = g_agg + r * 64 + l * 4;
    asm volatile("red.global.add.v4.f32 [%0], {%1, %2, %3, %4};"
                 :: "l"(dst), "f"(v.x * w), "f"(v.y * w), "f"(v.z * w), "f"(v.w * w)
                 : "memory");
}

// ---------------------------------------------------------------------------
// BN column stats (float4, high MLP) + fused finalize in the last block.
// ---------------------------------------------------------------------------
#define NSTAT_BLK 1184

__global__ __launch_bounds__(256) void k_colstats(const float* __restrict__ gamma,
                                                  const float* __restrict__ beta) {
    int j4 = threadIdx.x & 15;
    int grp = threadIdx.x >> 4;
    float4 s = make_float4(0.f, 0.f, 0.f, 0.f);
    float4 q = make_float4(0.f, 0.f, 0.f, 0.f);
    for (int r = blockIdx.x * 16 + grp; r < NN; r += NSTAT_BLK * 16) {
        float4 v = *reinterpret_cast<const float4*>(g_agg + r * 64 + j4 * 4);
        s.x += v.x; s.y += v.y; s.z += v.z; s.w += v.w;
        q.x = fmaf(v.x, v.x, q.x); q.y = fmaf(v.y, v.y, q.y);
        q.z = fmaf(v.z, v.z, q.z); q.w = fmaf(v.w, v.w, q.w);
    }
    __shared__ float ss[16][68], sq[16][68];
    __shared__ bool s_last;
    *reinterpret_cast<float4*>(&ss[grp][j4 * 4]) = s;
    *reinterpret_cast<float4*>(&sq[grp][j4 * 4]) = q;
    __syncthreads();
    if (threadIdx.x < 64) {
        int j = threadIdx.x;
        float S = 0.f, Q = 0.f;
#pragma unroll
        for (int g = 0; g < 16; g++) { S += ss[g][j]; Q += sq[g][j]; }
        atomicAdd(&g_sum[j], (double)S);
        atomicAdd(&g_sumsq[j], (double)Q);
    }
    __syncthreads();
    if (threadIdx.x == 0) {
        __threadfence();
        unsigned int prev = atomicAdd(&g_arrive, 1u);
        s_last = (prev == NSTAT_BLK - 1);
    }
    __syncthreads();
    if (s_last) {
        if (threadIdx.x < NH) {
            int j = threadIdx.x;
            double mean = g_sum[j] / (double)NN;
            double var = g_sumsq[j] / (double)NN - mean * mean;
            float sc = (float)((double)gamma[j] * rsqrt(var + 1e-5));
            g_scale[j] = sc;
            g_shift[j] = beta[j] - (float)mean * sc;
            g_sum[j] = 0.0;
            g_sumsq[j] = 0.0;
        }
        if (threadIdx.x == 64) g_arrive = 0u;
    }
}

// ---------------------------------------------------------------------------
// Epilogue: BN affine + ReLU + JAX threefry dropout (partitionable layout);
// re-zeroes g_agg for the next call.
// ---------------------------------------------------------------------------
#define TF_R(r) { x0 += x1; x1 = __funnelshift_l(x1, x1, (r)); x1 ^= x0; }

__device__ __forceinline__ uint32_t tf_bits(uint32_t i) {
    const uint32_t ks0 = 0u, ks1 = 42u, ks2 = 0x1BD11BDAu ^ 42u;
    uint32_t x0 = ks0;
    uint32_t x1 = i + ks1;
    TF_R(13) TF_R(15) TF_R(26) TF_R(6)
    x0 += ks1; x1 += ks2 + 1u;
    TF_R(17) TF_R(29) TF_R(16) TF_R(24)
    x0 += ks2; x1 += ks0 + 2u;
    TF_R(13) TF_R(15) TF_R(26) TF_R(6)
    x0 += ks0; x1 += ks1 + 3u;
    TF_R(17) TF_R(29) TF_R(16) TF_R(24)
    x0 += ks1; x1 += ks2 + 4u;
    TF_R(13) TF_R(15) TF_R(26) TF_R(6)
    x0 += ks2; x1 += ks0 + 5u;
    return x0 ^ x1;
}

__global__ void k_out(float* __restrict__ out) {
    int base = (blockIdx.x * blockDim.x + threadIdx.x) * 4;
    if (base >= NHTOT) return;
    float4 v4 = *reinterpret_cast<const float4*>(g_agg + base);
    *reinterpret_cast<float4*>(g_agg + base) = make_float4(0.f, 0.f, 0.f, 0.f);
    int j = base & 63;
    float vals[4] = {v4.x, v4.y, v4.z, v4.w};
    float res[4];
    const float inv_keep = 1.0f / 0.7f;
#pragma unroll
    for (int t = 0; t < 4; t++) {
        uint32_t bits = tf_bits((uint32_t)(base + t));
        float u = __uint_as_float((bits >> 9) | 0x3f800000u) - 1.0f;
        float v = fmaf(vals[t], g_scale[j + t], g_shift[j + t]);
        v = fmaxf(v, 0.0f);
        res[t] = (u < 0.7f) ? v * inv_keep : 0.0f;
    }
    *reinterpret_cast<float4*>(out + base) =
        make_float4(res[0], res[1], res[2], res[3]);
}

// ---------------------------------------------------------------------------
extern "C" void kernel_launch(void* const* d_in, const int* in_sizes, int n_in,
                              void* d_out, int out_size) {
    const float* x     = (const float*)d_in[0];
    const int*   row   = (const int*)d_in[1];
    const int*   col   = (const int*)d_in[2];
    const float* ew    = (const float*)d_in[3];
    const float* W     = (const float*)d_in[4];
    const float* gamma = (const float*)d_in[6];
    const float* beta  = (const float*)d_in[7];
    float* out = (float*)d_out;

    k_gemm<<<(NN + 127) / 128, 256>>>(x, W);
    k_scatter<<<(NE * 16) / 256, 256>>>(row, col, ew);
    k_colstats<<<NSTAT_BLK, 256>>>(gamma, beta);
    k_out<<<(NHTOT / 4 + 255) / 256, 256>>>(out);
}

// round 11
// speedup vs baseline: 1.1766x; 1.0007x over previous
#include <cuda_runtime.h>
#include <stdint.h>

#define NN 100000
#define NE 1600000
#define NF 256
#define NH 64
#define NHTOT (NN * NH)          // 6,400,000

// Scratch (static device globals — zero-initialized at load; each call restores
// the zero state itself so graph replays are deterministic).
__device__ __align__(16) float g_support[NHTOT];   // x @ W
__device__ __align__(16) float g_agg[NHTOT];       // segment_sum (bias cancels in BN)
__device__ double g_sum[NH];
__device__ double g_sumsq[NH];
__device__ float g_scale[NH];
__device__ float g_shift[NH];
__device__ unsigned int g_arrive;                  // colstats completion counter

// ---------------------------------------------------------------------------
// GEMM: support[NN,64] = x[NN,256] @ W[256,64] via mma.sync tf32 (m16n8k8).
// CTA: 256 threads / 8 warps; tile 128x64; warp w -> rows 16w..16w+15.
// K in 8 chunks of 32. Inputs rounded to tf32 (cvt.rna) at SMEM staging.
// ---------------------------------------------------------------------------
__device__ __forceinline__ float tf32r(float f) {
    uint32_t o;
    asm("cvt.rna.tf32.f32 %0, %1;" : "=r"(o) : "f"(f));
    return __uint_as_float(o);
}

__global__ __launch_bounds__(256) void k_gemm(const float* __restrict__ x,
                                              const float* __restrict__ W) {
    __shared__ float As[128][36];   // stride 36: banks 4r+c -> conflict-free frags
    __shared__ float Bs[32][68];    // stride 68: <=2-way

    const int tid = threadIdx.x;
    const int lane = tid & 31;
    const int warp = tid >> 5;
    const int rowBase = blockIdx.x * 128;
    const int r4 = lane >> 2;       // 0..7
    const int c4 = lane & 3;        // 0..3

    float d[8][4];
#pragma unroll
    for (int n = 0; n < 8; n++)
#pragma unroll
        for (int i = 0; i < 4; i++) d[n][i] = 0.0f;

    for (int ch = 0; ch < 8; ch++) {
        const int k0 = ch * 32;
#pragma unroll
        for (int i = 0; i < 4; i++) {
            int idx = i * 256 + tid;
            int r = idx >> 3, q = idx & 7;
            float4 v = make_float4(0.f, 0.f, 0.f, 0.f);
            if (rowBase + r < NN)
                v = __ldg(reinterpret_cast<const float4*>(x + (rowBase + r) * NF + k0) + q);
            v.x = tf32r(v.x); v.y = tf32r(v.y); v.z = tf32r(v.z); v.w = tf32r(v.w);
            *reinterpret_cast<float4*>(&As[r][q * 4]) = v;
        }
#pragma unroll
        for (int i = 0; i < 2; i++) {
            int idx = i * 256 + tid;
            int r = idx >> 4, q = idx & 15;
            float4 v = __ldg(reinterpret_cast<const float4*>(W + (k0 + r) * NH) + q);
            v.x = tf32r(v.x); v.y = tf32r(v.y); v.z = tf32r(v.z); v.w = tf32r(v.w);
            *reinterpret_cast<float4*>(&Bs[r][q * 4]) = v;
        }
        __syncthreads();

        const int wr = warp * 16;
#pragma unroll
        for (int k8 = 0; k8 < 4; k8++) {
            const int kc = k8 * 8;
            uint32_t a0 = __float_as_uint(As[wr + r4][kc + c4]);
            uint32_t a1 = __float_as_uint(As[wr + r4 + 8][kc + c4]);
            uint32_t a2 = __float_as_uint(As[wr + r4][kc + c4 + 4]);
            uint32_t a3 = __float_as_uint(As[wr + r4 + 8][kc + c4 + 4]);
#pragma unroll
            for (int n = 0; n < 8; n++) {
                uint32_t b0 = __float_as_uint(Bs[kc + c4][n * 8 + r4]);
                uint32_t b1 = __float_as_uint(Bs[kc + c4 + 4][n * 8 + r4]);
                asm volatile(
                    "mma.sync.aligned.m16n8k8.row.col.f32.tf32.tf32.f32 "
                    "{%0,%1,%2,%3}, {%4,%5,%6,%7}, {%8,%9}, {%0,%1,%2,%3};"
                    : "+f"(d[n][0]), "+f"(d[n][1]), "+f"(d[n][2]), "+f"(d[n][3])
                    : "r"(a0), "r"(a1), "r"(a2), "r"(a3), "r"(b0), "r"(b1));
            }
        }
        __syncthreads();
    }

    const int wr = warp * 16;
#pragma unroll
    for (int n = 0; n < 8; n++) {
        int gr = rowBase + wr + r4;
        int col = n * 8 + 2 * c4;
        if (gr < NN)
            *reinterpret_cast<float2*>(g_support + gr * NH + col) =
                make_float2(d[n][0], d[n][1]);
        if (gr + 8 < NN)
            *reinterpret_cast<float2*>(g_support + (gr + 8) * NH + col) =
                make_float2(d[n][2], d[n][3]);
    }
}

// ---------------------------------------------------------------------------
// Scatter: agg[row[e]] += ew[e] * support[col[e]]   (16 threads/edge, v4 red)
// ---------------------------------------------------------------------------
__global__ void k_scatter(const int* __restrict__ row, const int* __restrict__ col,
                          const float* __restrict__ ew) {
    int t = blockIdx.x * blockDim.x + threadIdx.x;
    int e = t >> 4;
    if (e >= NE) return;
    int l = t & 15;
    int c = __ldg(col + e);
    int r = __ldg(row + e);
    float w = __ldg(ew + e);
    float4 v = __ldg(reinterpret_cast<const float4*>(g_support) + c * 16 + l);
    float* dst = g_agg + r * 64 + l * 4;
    asm volatile("red.global.add.v4.f32 [%0], {%1, %2, %3, %4};"
                 :: "l"(dst), "f"(v.x * w), "f"(v.y * w), "f"(v.z * w), "f"(v.w * w)
                 : "memory");
}

// ---------------------------------------------------------------------------
// BN column stats (float4, high MLP) + fused finalize in the last block.
// ---------------------------------------------------------------------------
#define NSTAT_BLK 1184

__global__ __launch_bounds__(256) void k_colstats(const float* __restrict__ gamma,
                                                  const float* __restrict__ beta) {
    int j4 = threadIdx.x & 15;
    int grp = threadIdx.x >> 4;
    float4 s = make_float4(0.f, 0.f, 0.f, 0.f);
    float4 q = make_float4(0.f, 0.f, 0.f, 0.f);
    for (int r = blockIdx.x * 16 + grp; r < NN; r += NSTAT_BLK * 16) {
        float4 v = *reinterpret_cast<const float4*>(g_agg + r * 64 + j4 * 4);
        s.x += v.x; s.y += v.y; s.z += v.z; s.w += v.w;
        q.x = fmaf(v.x, v.x, q.x); q.y = fmaf(v.y, v.y, q.y);
        q.z = fmaf(v.z, v.z, q.z); q.w = fmaf(v.w, v.w, q.w);
    }
    __shared__ float ss[16][68], sq[16][68];
    __shared__ bool s_last;
    *reinterpret_cast<float4*>(&ss[grp][j4 * 4]) = s;
    *reinterpret_cast<float4*>(&sq[grp][j4 * 4]) = q;
    __syncthreads();
    if (threadIdx.x < 64) {
        int j = threadIdx.x;
        float S = 0.f, Q = 0.f;
#pragma unroll
        for (int g = 0; g < 16; g++) { S += ss[g][j]; Q += sq[g][j]; }
        atomicAdd(&g_sum[j], (double)S);
        atomicAdd(&g_sumsq[j], (double)Q);
    }
    __syncthreads();
    if (threadIdx.x == 0) {
        __threadfence();
        unsigned int prev = atomicAdd(&g_arrive, 1u);
        s_last = (prev == NSTAT_BLK - 1);
    }
    __syncthreads();
    if (s_last) {
        if (threadIdx.x < NH) {
            int j = threadIdx.x;
            double mean = g_sum[j] / (double)NN;
            double var = g_sumsq[j] / (double)NN - mean * mean;
            float sc = (float)((double)gamma[j] * rsqrt(var + 1e-5));
            g_scale[j] = sc;
            g_shift[j] = beta[j] - (float)mean * sc;
            g_sum[j] = 0.0;
            g_sumsq[j] = 0.0;
        }
        if (threadIdx.x == 64) g_arrive = 0u;
    }
}

// ---------------------------------------------------------------------------
// Epilogue: BN affine + ReLU + JAX threefry dropout (partitionable layout),
// 4 chains evaluated round-interleaved for ILP; re-zeroes g_agg.
// ---------------------------------------------------------------------------
#define TFR4(rot)                                                   \
    _Pragma("unroll")                                               \
    for (int t = 0; t < 4; t++) {                                   \
        x0[t] += x1[t];                                             \
        x1[t] = __funnelshift_l(x1[t], x1[t], (rot));               \
        x1[t] ^= x0[t];                                             \
    }
#define TFK4(ka, kb, rconst)                                        \
    _Pragma("unroll")                                               \
    for (int t = 0; t < 4; t++) {                                   \
        x0[t] += (ka);                                              \
        x1[t] += (kb) + (rconst);                                   \
    }

__global__ __launch_bounds__(256) void k_out(float* __restrict__ out) {
    int base = (blockIdx.x * blockDim.x + threadIdx.x) * 4;
    if (base >= NHTOT) return;

    const uint32_t ks0 = 0u, ks1 = 42u, ks2 = 0x1BD11BDAu ^ 42u;
    uint32_t x0[4], x1[4];
#pragma unroll
    for (int t = 0; t < 4; t++) {
        x0[t] = ks0;
        x1[t] = (uint32_t)(base + t) + ks1;
    }
    TFR4(13) TFR4(15) TFR4(26) TFR4(6)
    TFK4(ks1, ks2, 1u)
    TFR4(17) TFR4(29) TFR4(16) TFR4(24)
    TFK4(ks2, ks0, 2u)
    TFR4(13) TFR4(15) TFR4(26) TFR4(6)
    TFK4(ks0, ks1, 3u)
    TFR4(17) TFR4(29) TFR4(16) TFR4(24)
    TFK4(ks1, ks2, 4u)
    TFR4(13) TFR4(15) TFR4(26) TFR4(6)
    TFK4(ks2, ks0, 5u)

    float4 v4 = *reinterpret_cast<const float4*>(g_agg + base);
    *reinterpret_cast<float4*>(g_agg + base) = make_float4(0.f, 0.f, 0.f, 0.f);
    int j = base & 63;
    float4 sc = *reinterpret_cast<const float4*>(g_scale + j);
    float4 sh = *reinterpret_cast<const float4*>(g_shift + j);

    float vals[4] = {v4.x, v4.y, v4.z, v4.w};
    float scs[4] = {sc.x, sc.y, sc.z, sc.w};
    float shs[4] = {sh.x, sh.y, sh.z, sh.w};
    float res[4];
    const float inv_keep = 1.0f / 0.7f;
#pragma unroll
    for (int t = 0; t < 4; t++) {
        uint32_t bits = x0[t] ^ x1[t];
        float u = __uint_as_float((bits >> 9) | 0x3f800000u) - 1.0f;
        float v = fmaxf(fmaf(vals[t], scs[t], shs[t]), 0.0f);
        res[t] = (u < 0.7f) ? v * inv_keep : 0.0f;
    }
    *reinterpret_cast<float4*>(out + base) =
        make_float4(res[0], res[1], res[2], res[3]);
}

// ---------------------------------------------------------------------------
extern "C" void kernel_launch(void* const* d_in, const int* in_sizes, int n_in,
                              void* d_out, int out_size) {
    const float* x     = (const float*)d_in[0];
    const int*   row   = (const int*)d_in[1];
    const int*   col   = (const int*)d_in[2];
    const float* ew    = (const float*)d_in[3];
    const float* W     = (const float*)d_in[4];
    const float* gamma = (const float*)d_in[6];
    const float* beta  = (const float*)d_in[7];
    float* out = (float*)d_out;

    k_gemm<<<(NN + 127) / 128, 256>>>(x, W);
    k_scatter<<<(NE * 16) / 256, 256>>>(row, col, ew);
    k_colstats<<<NSTAT_BLK, 256>>>(gamma, beta);
    k_out<<<(NHTOT / 4 + 255) / 256, 256>>>(out);
}

// round 12
// speedup vs baseline: 1.1990x; 1.0190x over previous
#include <cuda_runtime.h>
#include <stdint.h>

#define NN 100000
#define NE 1600000
#define NF 256
#define NH 64
#define NHTOT (NN * NH)          // 6,400,000

// Scratch (static device globals — zero-initialized at load; each call restores
// the zero state itself so graph replays are deterministic).
__device__ __align__(16) float g_support[NHTOT];   // x @ W
__device__ __align__(16) float g_agg[NHTOT];       // segment_sum (bias cancels in BN)
__device__ double g_sum[NH];
__device__ double g_sumsq[NH];
__device__ float g_scale[NH];
__device__ float g_shift[NH];
__device__ unsigned int g_arrive;                  // colstats completion counter

// ---------------------------------------------------------------------------
// GEMM: support[NN,64] = x[NN,256] @ W[256,64] via mma.sync tf32 (m16n8k8).
// ---------------------------------------------------------------------------
__device__ __forceinline__ float tf32r(float f) {
    uint32_t o;
    asm("cvt.rna.tf32.f32 %0, %1;" : "=r"(o) : "f"(f));
    return __uint_as_float(o);
}

__global__ __launch_bounds__(256) void k_gemm(const float* __restrict__ x,
                                              const float* __restrict__ W) {
    __shared__ float As[128][36];
    __shared__ float Bs[32][68];

    const int tid = threadIdx.x;
    const int lane = tid & 31;
    const int warp = tid >> 5;
    const int rowBase = blockIdx.x * 128;
    const int r4 = lane >> 2;
    const int c4 = lane & 3;

    float d[8][4];
#pragma unroll
    for (int n = 0; n < 8; n++)
#pragma unroll
        for (int i = 0; i < 4; i++) d[n][i] = 0.0f;

    for (int ch = 0; ch < 8; ch++) {
        const int k0 = ch * 32;
#pragma unroll
        for (int i = 0; i < 4; i++) {
            int idx = i * 256 + tid;
            int r = idx >> 3, q = idx & 7;
            float4 v = make_float4(0.f, 0.f, 0.f, 0.f);
            if (rowBase + r < NN)
                v = __ldg(reinterpret_cast<const float4*>(x + (rowBase + r) * NF + k0) + q);
            v.x = tf32r(v.x); v.y = tf32r(v.y); v.z = tf32r(v.z); v.w = tf32r(v.w);
            *reinterpret_cast<float4*>(&As[r][q * 4]) = v;
        }
#pragma unroll
        for (int i = 0; i < 2; i++) {
            int idx = i * 256 + tid;
            int r = idx >> 4, q = idx & 15;
            float4 v = __ldg(reinterpret_cast<const float4*>(W + (k0 + r) * NH) + q);
            v.x = tf32r(v.x); v.y = tf32r(v.y); v.z = tf32r(v.z); v.w = tf32r(v.w);
            *reinterpret_cast<float4*>(&Bs[r][q * 4]) = v;
        }
        __syncthreads();

        const int wr = warp * 16;
#pragma unroll
        for (int k8 = 0; k8 < 4; k8++) {
            const int kc = k8 * 8;
            uint32_t a0 = __float_as_uint(As[wr + r4][kc + c4]);
            uint32_t a1 = __float_as_uint(As[wr + r4 + 8][kc + c4]);
            uint32_t a2 = __float_as_uint(As[wr + r4][kc + c4 + 4]);
            uint32_t a3 = __float_as_uint(As[wr + r4 + 8][kc + c4 + 4]);
#pragma unroll
            for (int n = 0; n < 8; n++) {
                uint32_t b0 = __float_as_uint(Bs[kc + c4][n * 8 + r4]);
                uint32_t b1 = __float_as_uint(Bs[kc + c4 + 4][n * 8 + r4]);
                asm volatile(
                    "mma.sync.aligned.m16n8k8.row.col.f32.tf32.tf32.f32 "
                    "{%0,%1,%2,%3}, {%4,%5,%6,%7}, {%8,%9}, {%0,%1,%2,%3};"
                    : "+f"(d[n][0]), "+f"(d[n][1]), "+f"(d[n][2]), "+f"(d[n][3])
                    : "r"(a0), "r"(a1), "r"(a2), "r"(a3), "r"(b0), "r"(b1));
            }
        }
        __syncthreads();
    }

    const int wr = warp * 16;
#pragma unroll
    for (int n = 0; n < 8; n++) {
        int gr = rowBase + wr + r4;
        int col = n * 8 + 2 * c4;
        if (gr < NN)
            *reinterpret_cast<float2*>(g_support + gr * NH + col) =
                make_float2(d[n][0], d[n][1]);
        if (gr + 8 < NN)
            *reinterpret_cast<float2*>(g_support + (gr + 8) * NH + col) =
                make_float2(d[n][2], d[n][3]);
    }
}

// ---------------------------------------------------------------------------
// Scatter: agg[row[e]] += ew[e] * support[col[e]]   (16 threads/edge, v4 red)
// ---------------------------------------------------------------------------
__global__ void k_scatter(const int* __restrict__ row, const int* __restrict__ col,
                          const float* __restrict__ ew) {
    int t = blockIdx.x * blockDim.x + threadIdx.x;
    int e = t >> 4;
    if (e >= NE) return;
    int l = t & 15;
    int c = __ldg(col + e);
    int r = __ldg(row + e);
    float w = __ldg(ew + e);
    float4 v = __ldg(reinterpret_cast<const float4*>(g_support) + c * 16 + l);
    float* dst = g_agg + r * 64 + l * 4;
    asm volatile("red.global.add.v4.f32 [%0], {%1, %2, %3, %4};"
                 :: "l"(dst), "f"(v.x * w), "f"(v.y * w), "f"(v.z * w), "f"(v.w * w)
                 : "memory");
}

// ---------------------------------------------------------------------------
// BN column stats (float4, high MLP) + fused finalize in the last block.
// ---------------------------------------------------------------------------
#define NSTAT_BLK 1184

__global__ __launch_bounds__(256) void k_colstats(const float* __restrict__ gamma,
                                                  const float* __restrict__ beta) {
    int j4 = threadIdx.x & 15;
    int grp = threadIdx.x >> 4;
    float4 s = make_float4(0.f, 0.f, 0.f, 0.f);
    float4 q = make_float4(0.f, 0.f, 0.f, 0.f);
    for (int r = blockIdx.x * 16 + grp; r < NN; r += NSTAT_BLK * 16) {
        float4 v = *reinterpret_cast<const float4*>(g_agg + r * 64 + j4 * 4);
        s.x += v.x; s.y += v.y; s.z += v.z; s.w += v.w;
        q.x = fmaf(v.x, v.x, q.x); q.y = fmaf(v.y, v.y, q.y);
        q.z = fmaf(v.z, v.z, q.z); q.w = fmaf(v.w, v.w, q.w);
    }
    __shared__ float ss[16][68], sq[16][68];
    __shared__ bool s_last;
    *reinterpret_cast<float4*>(&ss[grp][j4 * 4]) = s;
    *reinterpret_cast<float4*>(&sq[grp][j4 * 4]) = q;
    __syncthreads();
    if (threadIdx.x < 64) {
        int j = threadIdx.x;
        float S = 0.f, Q = 0.f;
#pragma unroll
        for (int g = 0; g < 16; g++) { S += ss[g][j]; Q += sq[g][j]; }
        atomicAdd(&g_sum[j], (double)S);
        atomicAdd(&g_sumsq[j], (double)Q);
    }
    __syncthreads();
    if (threadIdx.x == 0) {
        __threadfence();
        unsigned int prev = atomicAdd(&g_arrive, 1u);
        s_last = (prev == NSTAT_BLK - 1);
    }
    __syncthreads();
    if (s_last) {
        if (threadIdx.x < NH) {
            int j = threadIdx.x;
            double mean = g_sum[j] / (double)NN;
            double var = g_sumsq[j] / (double)NN - mean * mean;
            float sc = (float)((double)gamma[j] * rsqrt(var + 1e-5));
            g_scale[j] = sc;
            g_shift[j] = beta[j] - (float)mean * sc;
            g_sum[j] = 0.0;
            g_sumsq[j] = 0.0;
        }
        if (threadIdx.x == 64) g_arrive = 0u;
    }
}

// ---------------------------------------------------------------------------
// Epilogue: BN affine + ReLU + JAX threefry dropout (partitionable layout).
// 16 elements (4 coalesced float4 chunks, chunk stride 1024 floats) per thread:
// MLP=4 on the agg loads, one scale/shift load per thread, batched stores.
// Re-zeroes g_agg for the next call.
// ---------------------------------------------------------------------------
#define TFR4(rot)                                                   \
    _Pragma("unroll")                                               \
    for (int t = 0; t < 4; t++) {                                   \
        x0[t] += x1[t];                                             \
        x1[t] = __funnelshift_l(x1[t], x1[t], (rot));               \
        x1[t] ^= x0[t];                                             \
    }
#define TFK4(ka, kb, rconst)                                        \
    _Pragma("unroll")                                               \
    for (int t = 0; t < 4; t++) {                                   \
        x0[t] += (ka);                                              \
        x1[t] += (kb) + (rconst);                                   \
    }

__device__ __forceinline__ void tf_bits4(uint32_t base, uint32_t* bits) {
    const uint32_t ks0 = 0u, ks1 = 42u, ks2 = 0x1BD11BDAu ^ 42u;
    uint32_t x0[4], x1[4];
#pragma unroll
    for (int t = 0; t < 4; t++) {
        x0[t] = ks0;
        x1[t] = (base + (uint32_t)t) + ks1;
    }
    TFR4(13) TFR4(15) TFR4(26) TFR4(6)
    TFK4(ks1, ks2, 1u)
    TFR4(17) TFR4(29) TFR4(16) TFR4(24)
    TFK4(ks2, ks0, 2u)
    TFR4(13) TFR4(15) TFR4(26) TFR4(6)
    TFK4(ks0, ks1, 3u)
    TFR4(17) TFR4(29) TFR4(16) TFR4(24)
    TFK4(ks1, ks2, 4u)
    TFR4(13) TFR4(15) TFR4(26) TFR4(6)
    TFK4(ks2, ks0, 5u)
#pragma unroll
    for (int t = 0; t < 4; t++) bits[t] = x0[t] ^ x1[t];
}

__global__ __launch_bounds__(256) void k_out(float* __restrict__ out) {
    const int blockBase = blockIdx.x * 4096;         // 256 thr * 16 floats
    const int t4 = threadIdx.x * 4;
    const int base0 = blockBase + t4;

    // Batched loads: 4 chunks, stride 1024 floats (MLP=4)
    float4 v[4];
    bool ok[4];
#pragma unroll
    for (int c = 0; c < 4; c++) {
        int idx = base0 + c * 1024;
        ok[c] = idx < NHTOT;
        if (ok[c]) v[c] = *reinterpret_cast<const float4*>(g_agg + idx);
    }
    // Re-zero agg (batched stores; no dependency on compute)
#pragma unroll
    for (int c = 0; c < 4; c++)
        if (ok[c])
            *reinterpret_cast<float4*>(g_agg + base0 + c * 1024) =
                make_float4(0.f, 0.f, 0.f, 0.f);

    // Chunk stride 1024 ≡ 0 mod 64 -> same BN column for all chunks
    const int j = base0 & 63;
    float4 sc = *reinterpret_cast<const float4*>(g_scale + j);
    float4 sh = *reinterpret_cast<const float4*>(g_shift + j);
    const float scs[4] = {sc.x, sc.y, sc.z, sc.w};
    const float shs[4] = {sh.x, sh.y, sh.z, sh.w};
    const float inv_keep = 1.0f / 0.7f;

#pragma unroll
    for (int c = 0; c < 4; c++) {
        if (!ok[c]) continue;
        int idx = base0 + c * 1024;
        uint32_t bits[4];
        tf_bits4((uint32_t)idx, bits);
        float vals[4] = {v[c].x, v[c].y, v[c].z, v[c].w};
        float res[4];
#pragma unroll
        for (int t = 0; t < 4; t++) {
            float u = __uint_as_float((bits[t] >> 9) | 0x3f800000u) - 1.0f;
            float h = fmaxf(fmaf(vals[t], scs[t], shs[t]), 0.0f);
            res[t] = (u < 0.7f) ? h * inv_keep : 0.0f;
        }
        *reinterpret_cast<float4*>(out + idx) =
            make_float4(res[0], res[1], res[2], res[3]);
    }
}

// ---------------------------------------------------------------------------
extern "C" void kernel_launch(void* const* d_in, const int* in_sizes, int n_in,
                              void* d_out, int out_size) {
    const float* x     = (const float*)d_in[0];
    const int*   row   = (const int*)d_in[1];
    const int*   col   = (const int*)d_in[2];
    const float* ew    = (const float*)d_in[3];
    const float* W     = (const float*)d_in[4];
    const float* gamma = (const float*)d_in[6];
    const float* beta  = (const float*)d_in[7];
    float* out = (float*)d_out;

    k_gemm<<<(NN + 127) / 128, 256>>>(x, W);
    k_scatter<<<(NE * 16) / 256, 256>>>(row, col, ew);
    k_colstats<<<NSTAT_BLK, 256>>>(gamma, beta);
    k_out<<<(NHTOT + 4095) / 4096, 256>>>(out);
}